// round 5
// baseline (speedup 1.0000x reference)
#include <cuda_runtime.h>
#include <cstdint>

// ---------------------------------------------------------------------------
// BigramLM forward, GB300 sm_103a.
//   build_qkv: QT/KT/VT[t][v][f] tables (520 x 32 each)
//   build_qk : EQK[pair(t,s)][tok_t][tok_s][h] = exp(q.k * 32^-0.5)  (L2)
//   build_vf : VF[t][v][:] = VT[t][v] @ Wf + bf    (FF folded)
//   main     : 512 threads/block, ONE batch/thread (16 warps/SM), 128-bit
//              smem loads feeding fma.rn.f32x2, post-hoc softmax norm,
//              per-row smem-staged coalesced streaming stores.
// ---------------------------------------------------------------------------

#define VOCAB   65
#define NEMB    32
#define TBLK    8
#define NPAIR   36
#define NTV     (TBLK*VOCAB)        // 520

typedef unsigned long long u64;

__device__ __align__(16) float g_QT[NTV * NEMB];
__device__ __align__(16) float g_KT[NTV * NEMB];
__device__ __align__(16) float g_VT[NTV * NEMB];
__device__ __align__(16) float g_VF[NTV * NEMB];
__device__ __align__(16) float g_QK[NPAIR * VOCAB * VOCAB * 4];

// ---------------- packed f32x2 helpers --------------------------------------
__device__ __forceinline__ u64 pk2(float a, float b) {
    u64 r;
    asm("mov.b64 %0, {%1, %2};" : "=l"(r)
        : "r"(__float_as_uint(a)), "r"(__float_as_uint(b)));
    return r;
}
__device__ __forceinline__ void upk2(float& a, float& b, u64 p) {
    unsigned int x, y;
    asm("mov.b64 {%0, %1}, %2;" : "=r"(x), "=r"(y) : "l"(p));
    a = __uint_as_float(x); b = __uint_as_float(y);
}
__device__ __forceinline__ u64 fma2(u64 a, u64 b, u64 c) {
    u64 d;
    asm("fma.rn.f32x2 %0, %1, %2, %3;" : "=l"(d) : "l"(a), "l"(b), "l"(c));
    return d;
}
__device__ __forceinline__ u64 mul2(u64 a, u64 b) {
    u64 d;
    asm("mul.rn.f32x2 %0, %1, %2;" : "=l"(d) : "l"(a), "l"(b));
    return d;
}

// ---------------- stage 1: per-(t,vocab) q/k/v tables ------------------------
__global__ void build_qkv(const float* __restrict__ tok_emb,
                          const float* __restrict__ pos_emb,
                          const float* __restrict__ Wq,
                          const float* __restrict__ Wk,
                          const float* __restrict__ Wv) {
    int tv = blockIdx.x;            // 0..519
    int t  = tv / VOCAB;
    int v  = tv - t * VOCAB;
    int f  = threadIdx.x;           // 0..31 -> (h,d)
    int h  = f >> 3, d = f & 7;
    float qa = 0.f, ka = 0.f, va = 0.f;
#pragma unroll
    for (int c = 0; c < NEMB; c++) {
        float x = tok_emb[v * NEMB + c] + pos_emb[t * NEMB + c];
        int wi = (h * NEMB + c) * 8 + d;     // [H, C, hs]
        qa = fmaf(x, Wq[wi], qa);
        ka = fmaf(x, Wk[wi], ka);
        va = fmaf(x, Wv[wi], va);
    }
    g_QT[tv * NEMB + f] = qa;
    g_KT[tv * NEMB + f] = ka;
    g_VT[tv * NEMB + f] = va;
}

// ---------------- stage 2a: exp(attention-logit) table -----------------------
__global__ void build_qk() {
    int P = blockIdx.y;             // pair index 0..35
    int a = blockIdx.x;             // tok_t 0..64
    int t = 0, rem = P;
    while (rem > t) { rem -= (t + 1); t++; }
    int s = rem;
    const float scale = 0.17677669529663687f;   // 32^-0.5 (n_embed!)
    for (int u = threadIdx.x; u < VOCAB * 4; u += blockDim.x) {
        int b = u >> 2, h = u & 3;
        const float* qp = &g_QT[(t * VOCAB + a) * NEMB + h * 8];
        const float* kp = &g_KT[(s * VOCAB + b) * NEMB + h * 8];
        float acc = 0.f;
#pragma unroll
        for (int d = 0; d < 8; d++) acc = fmaf(qp[d], kp[d], acc);
        g_QK[((P * VOCAB + a) * VOCAB + b) * 4 + h] = __expf(acc * scale);
    }
}

// ---------------- stage 2b: fold FF into V table ------------------------------
__global__ void build_vf(const float* __restrict__ Wf,
                         const float* __restrict__ bf) {
    int tv = blockIdx.x;            // 0..519
    int j  = threadIdx.x;           // 0..31
    const float* vr = g_VT + tv * NEMB;
    float acc = bf[j];
#pragma unroll
    for (int c = 0; c < NEMB; c++)
        acc = fmaf(vr[c], Wf[c * NEMB + j], acc);
    g_VF[tv * NEMB + j] = acc;
}

// ---------------- stage 3: main ----------------------------------------------
// smem float offsets
#define SVF  0                          // VF rows padded to 36 floats (16B ok)
#define SWL  (NTV * 36)                 // 18720 ; Wl rows padded to 68
#define SBL  (SWL + 32 * 68)            // 20896 ; bl (68, padded)
#define STG  (SBL + 68)                 // 20964 ; staging [512][66]
#define SMEM_FLOATS (STG + 512 * 66)    // 54756
#define SMEM_BYTES  (SMEM_FLOATS * 4)   // 219,024 bytes

#define NTHR 512

template<int T>
__device__ __forceinline__ void do_row(const float4* __restrict__ QK4,
                                       const float* __restrict__ sm,
                                       const int* __restrict__ tok,
                                       float* __restrict__ stg)
{
    const int base = T * (T + 1) / 2;
    const int r = tok[T] * VOCAB;
    float4 s4 = make_float4(0.f, 0.f, 0.f, 0.f);
    u64 h[16];
#pragma unroll
    for (int g = 0; g < 16; g++) h[g] = 0ULL;

#pragma unroll
    for (int s = 0; s <= T; s++) {
        float4 e = __ldg(&QK4[(base + s) * (VOCAB * VOCAB) + r + tok[s]]);
        s4.x += e.x; s4.y += e.y; s4.z += e.z; s4.w += e.w;
        u64 w[4] = { pk2(e.x, e.x), pk2(e.y, e.y),
                     pk2(e.z, e.z), pk2(e.w, e.w) };
        const ulonglong2* vv =
            (const ulonglong2*)(sm + SVF + (s * VOCAB + tok[s]) * 36);
#pragma unroll
        for (int g = 0; g < 8; g++) {
            ulonglong2 p = vv[g];
            h[2 * g]     = fma2(w[(2 * g) >> 2],     p.x, h[2 * g]);
            h[2 * g + 1] = fma2(w[(2 * g + 1) >> 2], p.y, h[2 * g + 1]);
        }
    }

    // post-hoc softmax normalization + relu
    u64 inv[4];
    {
        float a = __fdividef(1.f, s4.x), b = __fdividef(1.f, s4.y);
        float c = __fdividef(1.f, s4.z), d = __fdividef(1.f, s4.w);
        inv[0] = pk2(a, a); inv[1] = pk2(b, b);
        inv[2] = pk2(c, c); inv[3] = pk2(d, d);
    }
    float y[32];
#pragma unroll
    for (int g = 0; g < 16; g++) {
        float u, v;
        upk2(u, v, mul2(h[g], inv[g >> 2]));
        y[2 * g] = fmaxf(u, 0.f);
        y[2 * g + 1] = fmaxf(v, 0.f);
    }

    // ---- logits, two halves of 32 outputs (+ v=64) ----
#pragma unroll
    for (int h2 = 0; h2 < 2; h2++) {
        u64 z[16];
        const u64* bl2 = (const u64*)(sm + SBL) + h2 * 16;
#pragma unroll
        for (int v = 0; v < 16; v++) z[v] = bl2[v];
        float z64 = sm[SBL + 64];
#pragma unroll
        for (int j = 0; j < 32; j++) {
            u64 p = pk2(y[j], y[j]);
            const ulonglong2* w2 =
                (const ulonglong2*)(sm + SWL + j * 68 + h2 * 32);
#pragma unroll
            for (int g = 0; g < 8; g++) {
                ulonglong2 w = w2[g];
                z[2 * g]     = fma2(p, w.x, z[2 * g]);
                z[2 * g + 1] = fma2(p, w.y, z[2 * g + 1]);
            }
            if (h2 == 1)
                z64 = fmaf(y[j], sm[SWL + j * 68 + 64], z64);
        }
        if ((T & 1) == 0) {
            // even row: staging S[k] = z[k]; u64 stores aligned
            u64* d2 = (u64*)stg;
#pragma unroll
            for (int v = 0; v < 16; v++) d2[h2 * 16 + v] = z[v];
            if (h2 == 1) stg[64] = z64;
        } else {
            // odd row: S[0]=z[0], S[m+1]=z[m] (m>=1) so flush u64s stay aligned
#pragma unroll
            for (int v = 0; v < 16; v++) {
                float u, w;
                int k = h2 * 32 + 2 * v;
                upk2(u, w, z[v]);
                stg[k == 0 ? 0 : k + 1] = u;
                stg[k + 2] = w;
            }
            if (h2 == 1) stg[65] = z64;
        }
    }
}

__global__ __launch_bounds__(NTHR, 1)
void bigram_main(const int* __restrict__ idx,
                 const float* __restrict__ Wl, const float* __restrict__ bl,
                 float* __restrict__ out, int nb) {
    extern __shared__ float sm[];
    int tid = threadIdx.x;

    // --- cooperative smem fill (VF row = 32 floats = 8 ulonglong2) ---
    for (int r = tid; r < NTV; r += NTHR) {
        const ulonglong2* src = (const ulonglong2*)(g_VF + r * NEMB);
        ulonglong2* dst = (ulonglong2*)(sm + SVF + r * 36);
#pragma unroll
        for (int g = 0; g < 8; g++) dst[g] = src[g];
    }
    for (int i = tid; i < 32 * 68; i += NTHR) {
        int j = i / 68, v = i - j * 68;
        sm[SWL + i] = (v < 65) ? Wl[j * 65 + v] : 0.f;
    }
    if (tid < 68) sm[SBL + tid] = (tid < 65) ? bl[tid] : 0.f;
    __syncthreads();

    const float4* QK4 = (const float4*)g_QK;
    int ntile = (nb + NTHR - 1) / NTHR;

    for (int tile = blockIdx.x; tile < ntile; tile += gridDim.x) {
        int gbase = tile * NTHR;
        int b = gbase + tid;
        int bc = min(b, nb - 1);
        int tok[8];
        {
            const int4* pa = (const int4*)(idx + (size_t)bc * 8);
            int4 x0 = __ldg(pa), x1 = __ldg(pa + 1);
            tok[0] = x0.x; tok[1] = x0.y; tok[2] = x0.z; tok[3] = x0.w;
            tok[4] = x1.x; tok[5] = x1.y; tok[6] = x1.z; tok[7] = x1.w;
        }
        float* stg = sm + STG + tid * 66;

#define ROW(T)                                                              \
        do_row<T>(QK4, sm, tok, stg);                                       \
        __syncthreads();                                                    \
        {                                                                   \
            const int srcoff = ((T) & 1) ? 2 : 0;                           \
            const int dstoff = ((T) & 1) ? 1 : 0;                           \
            for (int i = tid; i < 512 * 32; i += NTHR) {                    \
                int row = i >> 5, g = i & 31;                               \
                int bb = gbase + row;                                       \
                if (bb < nb) {                                              \
                    u64 val = *(const u64*)(sm + STG + row * 66             \
                                            + srcoff + 2 * g);              \
                    __stcs((u64*)(out + (size_t)bb * 520 + (T) * 65         \
                                  + dstoff) + g, val);                      \
                }                                                           \
            }                                                               \
            for (int i = tid; i < 512; i += NTHR) {                         \
                int bb = gbase + i;                                         \
                if (bb < nb) {                                              \
                    int so = ((T) & 1) ? 0 : 64;                            \
                    int go = ((T) & 1) ? 0 : 64;                            \
                    __stcs(out + (size_t)bb * 520 + (T) * 65 + go,          \
                           sm[STG + i * 66 + so]);                          \
                }                                                           \
            }                                                               \
        }                                                                   \
        __syncthreads();

        ROW(0) ROW(1) ROW(2) ROW(3) ROW(4) ROW(5) ROW(6) ROW(7)
#undef ROW
    }
}

// ---------------------------------------------------------------------------
extern "C" void kernel_launch(void* const* d_in, const int* in_sizes, int n_in,
                              void* d_out, int out_size) {
    const int*   idx     = (const int*)  d_in[0];
    const float* tok_emb = (const float*)d_in[1];
    const float* pos_emb = (const float*)d_in[2];
    const float* Wq      = (const float*)d_in[3];
    const float* Wk      = (const float*)d_in[4];
    const float* Wv      = (const float*)d_in[5];
    const float* Wf      = (const float*)d_in[6];
    const float* bf      = (const float*)d_in[7];
    const float* Wl      = (const float*)d_in[8];
    const float* bl      = (const float*)d_in[9];
    float* out = (float*)d_out;

    int nb = in_sizes[0] / TBLK;   // 131072

    cudaFuncSetAttribute(bigram_main,
                         cudaFuncAttributeMaxDynamicSharedMemorySize, SMEM_BYTES);

    int dev = 0, nsm = 148;
    cudaGetDevice(&dev);
    cudaDeviceGetAttribute(&nsm, cudaDevAttrMultiProcessorCount, dev);

    build_qkv<<<NTV, 32>>>(tok_emb, pos_emb, Wq, Wk, Wv);
    build_qk<<<dim3(VOCAB, NPAIR), 256>>>();
    build_vf<<<NTV, 32>>>(Wf, bf);

    bigram_main<<<nsm, NTHR, SMEM_BYTES>>>(idx, Wl, bl, out, nb);
}

// round 6
// speedup vs baseline: 1.2693x; 1.2693x over previous
#include <cuda_runtime.h>
#include <cstdint>

// ---------------------------------------------------------------------------
// BigramLM forward, GB300 sm_103a.
//   build_qkv: QT/KT/VT[t][v][f] tables (520 x 32 each)
//   build_qk : EQK[pair(t,s)][tok_t][tok_s][h] = exp(q.k * 32^-0.5)  (L2)
//   build_vf : VF[t][v][:] = VT[t][v] @ Wf + bf    (FF folded)
//   main     : one batch/thread, row-PAIR processing (VF rows + Wl loads
//              shared across rows t,t+1), exp-table attention, post-hoc
//              softmax norm, packed fma.rn.f32x2, VF pad 34 (bank spread),
//              smem-staged coalesced streaming stores.
// ---------------------------------------------------------------------------

#define VOCAB   65
#define NEMB    32
#define TBLK    8
#define NPAIR   36
#define NTV     (TBLK*VOCAB)        // 520

typedef unsigned long long u64;

__device__ __align__(16) float g_QT[NTV * NEMB];
__device__ __align__(16) float g_KT[NTV * NEMB];
__device__ __align__(16) float g_VT[NTV * NEMB];
__device__ __align__(16) float g_VF[NTV * NEMB];
__device__ __align__(16) float g_QK[NPAIR * VOCAB * VOCAB * 4];

// ---------------- packed f32x2 helpers --------------------------------------
__device__ __forceinline__ u64 pk2(float a, float b) {
    u64 r;
    asm("mov.b64 %0, {%1, %2};" : "=l"(r)
        : "r"(__float_as_uint(a)), "r"(__float_as_uint(b)));
    return r;
}
__device__ __forceinline__ void upk2(float& a, float& b, u64 p) {
    unsigned int x, y;
    asm("mov.b64 {%0, %1}, %2;" : "=r"(x), "=r"(y) : "l"(p));
    a = __uint_as_float(x); b = __uint_as_float(y);
}
__device__ __forceinline__ u64 fma2(u64 a, u64 b, u64 c) {
    u64 d;
    asm("fma.rn.f32x2 %0, %1, %2, %3;" : "=l"(d) : "l"(a), "l"(b), "l"(c));
    return d;
}
__device__ __forceinline__ u64 mul2(u64 a, u64 b) {
    u64 d;
    asm("mul.rn.f32x2 %0, %1, %2;" : "=l"(d) : "l"(a), "l"(b));
    return d;
}

// ---------------- stage 1: per-(t,vocab) q/k/v tables ------------------------
__global__ void build_qkv(const float* __restrict__ tok_emb,
                          const float* __restrict__ pos_emb,
                          const float* __restrict__ Wq,
                          const float* __restrict__ Wk,
                          const float* __restrict__ Wv) {
    int tv = blockIdx.x;            // 0..519
    int t  = tv / VOCAB;
    int v  = tv - t * VOCAB;
    int f  = threadIdx.x;           // 0..31 -> (h,d)
    int h  = f >> 3, d = f & 7;
    float qa = 0.f, ka = 0.f, va = 0.f;
#pragma unroll
    for (int c = 0; c < NEMB; c++) {
        float x = tok_emb[v * NEMB + c] + pos_emb[t * NEMB + c];
        int wi = (h * NEMB + c) * 8 + d;     // [H, C, hs]
        qa = fmaf(x, Wq[wi], qa);
        ka = fmaf(x, Wk[wi], ka);
        va = fmaf(x, Wv[wi], va);
    }
    g_QT[tv * NEMB + f] = qa;
    g_KT[tv * NEMB + f] = ka;
    g_VT[tv * NEMB + f] = va;
}

// ---------------- stage 2a: exp(attention-logit) table -----------------------
__global__ void build_qk() {
    int P = blockIdx.y;             // pair index 0..35
    int a = blockIdx.x;             // tok_t 0..64
    int t = 0, rem = P;
    while (rem > t) { rem -= (t + 1); t++; }
    int s = rem;
    const float scale = 0.17677669529663687f;   // 32^-0.5 (n_embed!)
    for (int u = threadIdx.x; u < VOCAB * 4; u += blockDim.x) {
        int b = u >> 2, h = u & 3;
        const float* qp = &g_QT[(t * VOCAB + a) * NEMB + h * 8];
        const float* kp = &g_KT[(s * VOCAB + b) * NEMB + h * 8];
        float acc = 0.f;
#pragma unroll
        for (int d = 0; d < 8; d++) acc = fmaf(qp[d], kp[d], acc);
        g_QK[((P * VOCAB + a) * VOCAB + b) * 4 + h] = __expf(acc * scale);
    }
}

// ---------------- stage 2b: fold FF into V table ------------------------------
__global__ void build_vf(const float* __restrict__ Wf,
                         const float* __restrict__ bf) {
    int tv = blockIdx.x;            // 0..519
    int j  = threadIdx.x;           // 0..31
    const float* vr = g_VT + tv * NEMB;
    float acc = bf[j];
#pragma unroll
    for (int c = 0; c < NEMB; c++)
        acc = fmaf(vr[c], Wf[c * NEMB + j], acc);
    g_VF[tv * NEMB + j] = acc;
}

// ---------------- stage 3: main ----------------------------------------------
// smem float offsets
#define VFP  34                          // VF row pad: gcd(34,32)=2 -> 16 bank classes
#define SVF  0                           // 520 x 34
#define SWL  (NTV * VFP)                 // 17680 ; Wl rows padded to 68 (16B aligned)
#define SBL  (SWL + 32 * 68)             // 19856 ; bl (68, padded)
#define STG  (SBL + 68)                  // 19924 ; staging [256][130]
#define SMEM_FLOATS (STG + 256 * 130)    // 53204
#define SMEM_BYTES  (SMEM_FLOATS * 4)    // 212,816 bytes

template<int TA>
__device__ __forceinline__ void process_pair(const float4* __restrict__ QK4,
                                             const float* __restrict__ sm,
                                             const int* __restrict__ tok,
                                             float* __restrict__ srow)
{
    constexpr int TB = TA + 1;
    const int baseA = TA * (TA + 1) / 2;
    const int baseB = baseA + TA + 1;
    const int rA = tok[TA] * VOCAB;
    const int rB = tok[TB] * VOCAB;

    float4 sA = make_float4(0.f, 0.f, 0.f, 0.f);
    float4 sB = make_float4(0.f, 0.f, 0.f, 0.f);
    u64 hA[16], hB[16];
#pragma unroll
    for (int g = 0; g < 16; g++) { hA[g] = 0ULL; hB[g] = 0ULL; }

    // ---- shared-s combine: VF row loaded ONCE for both rows TA,TB ----
#pragma unroll
    for (int s = 0; s <= TA; s++) {
        float4 eA = __ldg(&QK4[(baseA + s) * (VOCAB * VOCAB) + rA + tok[s]]);
        float4 eB = __ldg(&QK4[(baseB + s) * (VOCAB * VOCAB) + rB + tok[s]]);
        sA.x += eA.x; sA.y += eA.y; sA.z += eA.z; sA.w += eA.w;
        sB.x += eB.x; sB.y += eB.y; sB.z += eB.z; sB.w += eB.w;
        u64 wA[4] = { pk2(eA.x, eA.x), pk2(eA.y, eA.y),
                      pk2(eA.z, eA.z), pk2(eA.w, eA.w) };
        u64 wB[4] = { pk2(eB.x, eB.x), pk2(eB.y, eB.y),
                      pk2(eB.z, eB.z), pk2(eB.w, eB.w) };
        const u64* v2 = (const u64*)(sm + SVF + (s * VOCAB + tok[s]) * VFP);
#pragma unroll
        for (int g = 0; g < 16; g++) {
            u64 r = v2[g];
            hA[g] = fma2(wA[g >> 2], r, hA[g]);
            hB[g] = fma2(wB[g >> 2], r, hB[g]);
        }
    }
    {   // extra s = TB term, row B only
        float4 eB = __ldg(&QK4[(baseB + TB) * (VOCAB * VOCAB) + rB + tok[TB]]);
        sB.x += eB.x; sB.y += eB.y; sB.z += eB.z; sB.w += eB.w;
        u64 wB[4] = { pk2(eB.x, eB.x), pk2(eB.y, eB.y),
                      pk2(eB.z, eB.z), pk2(eB.w, eB.w) };
        const u64* v2 = (const u64*)(sm + SVF + (TB * VOCAB + tok[TB]) * VFP);
#pragma unroll
        for (int g = 0; g < 16; g++)
            hB[g] = fma2(wB[g >> 2], v2[g], hB[g]);
    }

    // ---- post-hoc softmax normalization + relu ----
    u64 iA[4], iB[4];
    {
        float a = __fdividef(1.f, sA.x), b = __fdividef(1.f, sA.y);
        float c = __fdividef(1.f, sA.z), d = __fdividef(1.f, sA.w);
        iA[0] = pk2(a, a); iA[1] = pk2(b, b); iA[2] = pk2(c, c); iA[3] = pk2(d, d);
        a = __fdividef(1.f, sB.x); b = __fdividef(1.f, sB.y);
        c = __fdividef(1.f, sB.z); d = __fdividef(1.f, sB.w);
        iB[0] = pk2(a, a); iB[1] = pk2(b, b); iB[2] = pk2(c, c); iB[3] = pk2(d, d);
    }
    float yA[32], yB[32];
#pragma unroll
    for (int g = 0; g < 16; g++) {
        float u, v;
        upk2(u, v, mul2(hA[g], iA[g >> 2]));
        yA[2 * g] = fmaxf(u, 0.f); yA[2 * g + 1] = fmaxf(v, 0.f);
        upk2(u, v, mul2(hB[g], iB[g >> 2]));
        yB[2 * g] = fmaxf(u, 0.f); yB[2 * g + 1] = fmaxf(v, 0.f);
    }

    // ---- logits, Wl loads shared across rows; two halves of 32 (+ v=64) ----
#pragma unroll
    for (int h2 = 0; h2 < 2; h2++) {
        u64 zA[16], zB[16];
        const u64* bl2 = (const u64*)(sm + SBL) + h2 * 16;
#pragma unroll
        for (int v = 0; v < 16; v++) { zA[v] = bl2[v]; zB[v] = bl2[v]; }
        float z64A = sm[SBL + 64], z64B = z64A;
#pragma unroll
        for (int j = 0; j < 32; j++) {
            u64 pA = pk2(yA[j], yA[j]);
            u64 pB = pk2(yB[j], yB[j]);
            const ulonglong2* w2 =
                (const ulonglong2*)(sm + SWL + j * 68 + h2 * 32);
#pragma unroll
            for (int g = 0; g < 8; g++) {
                ulonglong2 w = w2[g];
                zA[2 * g]     = fma2(pA, w.x, zA[2 * g]);
                zA[2 * g + 1] = fma2(pA, w.y, zA[2 * g + 1]);
                zB[2 * g]     = fma2(pB, w.x, zB[2 * g]);
                zB[2 * g + 1] = fma2(pB, w.y, zB[2 * g + 1]);
            }
            if (h2 == 1) {
                float wl = sm[SWL + j * 68 + 64];
                z64A = fmaf(yA[j], wl, z64A);
                z64B = fmaf(yB[j], wl, z64B);
            }
        }
        // staging layout per batch: [rowA floats 0..64 | rowB floats 65..129]
        u64* dA = (u64*)srow;                    // rowA: u64-aligned
#pragma unroll
        for (int v = 0; v < 16; v++) dA[h2 * 16 + v] = zA[v];
#pragma unroll
        for (int v = 0; v < 16; v++) {           // rowB: scalar (odd base)
            float u, w; upk2(u, w, zB[v]);
            srow[65 + h2 * 32 + 2 * v]     = u;
            srow[65 + h2 * 32 + 2 * v + 1] = w;
        }
        if (h2 == 1) { srow[64] = z64A; srow[129] = z64B; }
    }
}

__global__ __launch_bounds__(256, 1)
void bigram_main(const int* __restrict__ idx,
                 const float* __restrict__ Wl, const float* __restrict__ bl,
                 float* __restrict__ out, int nb) {
    extern __shared__ float sm[];
    int tid = threadIdx.x;

    // --- cooperative smem fill (VF row = 32 floats = 16 u64) ---
    for (int r = tid; r < NTV; r += 256) {
        const u64* src = (const u64*)(g_VF + r * NEMB);
        u64* dst = (u64*)(sm + SVF + r * VFP);
#pragma unroll
        for (int g = 0; g < 16; g++) dst[g] = src[g];
    }
    for (int i = tid; i < 32 * 68; i += 256) {
        int j = i / 68, v = i - j * 68;
        sm[SWL + i] = (v < 65) ? Wl[j * 65 + v] : 0.f;
    }
    if (tid < 68) sm[SBL + tid] = (tid < 65) ? bl[tid] : 0.f;
    __syncthreads();

    const float4* QK4 = (const float4*)g_QK;
    int ntile = (nb + 255) >> 8;

    for (int tile = blockIdx.x; tile < ntile; tile += gridDim.x) {
        int gbase = tile << 8;
        int b = gbase + tid;
        int bc = min(b, nb - 1);
        int tok[8];
        {
            const int4* pa = (const int4*)(idx + (size_t)bc * 8);
            int4 x0 = __ldg(pa), x1 = __ldg(pa + 1);
            tok[0] = x0.x; tok[1] = x0.y; tok[2] = x0.z; tok[3] = x0.w;
            tok[4] = x1.x; tok[5] = x1.y; tok[6] = x1.z; tok[7] = x1.w;
        }
        float* srow = sm + STG + tid * 130;
        const u64* stg64 = (const u64*)(sm + STG);

        // Each pair computes rows (TA, TA+1) then flushes 130 contiguous
        // floats per batch = 65 u64, coalesced streaming stores.
#define DO_PAIR(TA)                                                         \
        {                                                                   \
            process_pair<TA>(QK4, sm, tok, srow);                           \
            __syncthreads();                                                \
            for (int u = tid; u < 256 * 65; u += 256) {                     \
                int b2 = u / 65, e = u - b2 * 65;                           \
                int gb = gbase + b2;                                        \
                if (gb < nb) {                                              \
                    u64 val = stg64[b2 * 65 + e];                           \
                    __stcs((u64*)(out + (size_t)gb * 520 + (TA) * 65) + e,  \
                           val);                                            \
                }                                                           \
            }                                                               \
            __syncthreads();                                                \
        }

        DO_PAIR(0)
        DO_PAIR(2)
        DO_PAIR(4)
        DO_PAIR(6)
#undef DO_PAIR
    }
}

// ---------------------------------------------------------------------------
extern "C" void kernel_launch(void* const* d_in, const int* in_sizes, int n_in,
                              void* d_out, int out_size) {
    const int*   idx     = (const int*)  d_in[0];
    const float* tok_emb = (const float*)d_in[1];
    const float* pos_emb = (const float*)d_in[2];
    const float* Wq      = (const float*)d_in[3];
    const float* Wk      = (const float*)d_in[4];
    const float* Wv      = (const float*)d_in[5];
    const float* Wf      = (const float*)d_in[6];
    const float* bf      = (const float*)d_in[7];
    const float* Wl      = (const float*)d_in[8];
    const float* bl      = (const float*)d_in[9];
    float* out = (float*)d_out;

    int nb = in_sizes[0] / TBLK;   // 131072

    cudaFuncSetAttribute(bigram_main,
                         cudaFuncAttributeMaxDynamicSharedMemorySize, SMEM_BYTES);

    int dev = 0, nsm = 148;
    cudaGetDevice(&dev);
    cudaDeviceGetAttribute(&nsm, cudaDevAttrMultiProcessorCount, dev);

    build_qkv<<<NTV, 32>>>(tok_emb, pos_emb, Wq, Wk, Wv);
    build_qk<<<dim3(VOCAB, NPAIR), 256>>>();
    build_vf<<<NTV, 32>>>(Wf, bf);

    bigram_main<<<nsm, 256, SMEM_BYTES>>>(idx, Wl, bl, out, nb);
}

// round 7
// speedup vs baseline: 1.3525x; 1.0656x over previous
#include <cuda_runtime.h>
#include <cstdint>

// ---------------------------------------------------------------------------
// BigramLM forward, GB300 sm_103a.
//   build_qkv: QT/KT/VT[t][v][f] tables (520 x 32 each)
//   build_qk : EQK[pair(t,s)][tok_t][tok_s][h] = exp(q.k * 32^-0.5)  (L2)
//   build_vf : VF[t][v][:] = VT[t][v] @ Wf + bf    (FF folded)
//   main     : scalar attention+VF per thread -> y[32] in smem (tf32 hi/lo),
//              logits via mma.sync.m16n8k8.tf32, 3-pass split (fp32-accurate),
//              direct fragment stores. Odd rows use col-window [1..64] with
//              col 0 scalar (even rows: [0..63] + col 64 scalar) so every
//              float2 global store is 8B-aligned.
// ---------------------------------------------------------------------------

#define VOCAB   65
#define NEMB    32
#define TBLK    8
#define NPAIR   36
#define NTV     (TBLK*VOCAB)        // 520

typedef unsigned long long u64;

__device__ __align__(16) float g_QT[NTV * NEMB];
__device__ __align__(16) float g_KT[NTV * NEMB];
__device__ __align__(16) float g_VT[NTV * NEMB];
__device__ __align__(16) float g_VF[NTV * NEMB];
__device__ __align__(16) float g_QK[NPAIR * VOCAB * VOCAB * 4];

// ---------------- packed f32x2 helpers --------------------------------------
__device__ __forceinline__ u64 pk2(float a, float b) {
    u64 r;
    asm("mov.b64 %0, {%1, %2};" : "=l"(r)
        : "r"(__float_as_uint(a)), "r"(__float_as_uint(b)));
    return r;
}
__device__ __forceinline__ void upk2(float& a, float& b, u64 p) {
    unsigned int x, y;
    asm("mov.b64 {%0, %1}, %2;" : "=r"(x), "=r"(y) : "l"(p));
    a = __uint_as_float(x); b = __uint_as_float(y);
}
__device__ __forceinline__ u64 fma2(u64 a, u64 b, u64 c) {
    u64 d;
    asm("fma.rn.f32x2 %0, %1, %2, %3;" : "=l"(d) : "l"(a), "l"(b), "l"(c));
    return d;
}
__device__ __forceinline__ u64 mul2(u64 a, u64 b) {
    u64 d;
    asm("mul.rn.f32x2 %0, %1, %2;" : "=l"(d) : "l"(a), "l"(b));
    return d;
}
__device__ __forceinline__ unsigned int tf32h(float x) {
    unsigned int r;
    asm("cvt.rna.tf32.f32 %0, %1;" : "=r"(r) : "f"(x));
    return r;
}
__device__ __forceinline__ void mma8(float* d, const unsigned int* a,
                                     const unsigned int* b) {
    asm volatile(
        "mma.sync.aligned.m16n8k8.row.col.f32.tf32.tf32.f32 "
        "{%0,%1,%2,%3}, {%4,%5,%6,%7}, {%8,%9}, {%0,%1,%2,%3};"
        : "+f"(d[0]), "+f"(d[1]), "+f"(d[2]), "+f"(d[3])
        : "r"(a[0]), "r"(a[1]), "r"(a[2]), "r"(a[3]), "r"(b[0]), "r"(b[1]));
}

// ---------------- stage 1: per-(t,vocab) q/k/v tables ------------------------
__global__ void build_qkv(const float* __restrict__ tok_emb,
                          const float* __restrict__ pos_emb,
                          const float* __restrict__ Wq,
                          const float* __restrict__ Wk,
                          const float* __restrict__ Wv) {
    int tv = blockIdx.x;            // 0..519
    int t  = tv / VOCAB;
    int v  = tv - t * VOCAB;
    int f  = threadIdx.x;           // 0..31 -> (h,d)
    int h  = f >> 3, d = f & 7;
    float qa = 0.f, ka = 0.f, va = 0.f;
#pragma unroll
    for (int c = 0; c < NEMB; c++) {
        float x = tok_emb[v * NEMB + c] + pos_emb[t * NEMB + c];
        int wi = (h * NEMB + c) * 8 + d;     // [H, C, hs]
        qa = fmaf(x, Wq[wi], qa);
        ka = fmaf(x, Wk[wi], ka);
        va = fmaf(x, Wv[wi], va);
    }
    g_QT[tv * NEMB + f] = qa;
    g_KT[tv * NEMB + f] = ka;
    g_VT[tv * NEMB + f] = va;
}

// ---------------- stage 2a: exp(attention-logit) table -----------------------
__global__ void build_qk() {
    int P = blockIdx.y;             // pair index 0..35
    int a = blockIdx.x;             // tok_t 0..64
    int t = 0, rem = P;
    while (rem > t) { rem -= (t + 1); t++; }
    int s = rem;
    const float scale = 0.17677669529663687f;   // 32^-0.5 (n_embed!)
    for (int u = threadIdx.x; u < VOCAB * 4; u += blockDim.x) {
        int b = u >> 2, h = u & 3;
        const float* qp = &g_QT[(t * VOCAB + a) * NEMB + h * 8];
        const float* kp = &g_KT[(s * VOCAB + b) * NEMB + h * 8];
        float acc = 0.f;
#pragma unroll
        for (int d = 0; d < 8; d++) acc = fmaf(qp[d], kp[d], acc);
        g_QK[((P * VOCAB + a) * VOCAB + b) * 4 + h] = __expf(acc * scale);
    }
}

// ---------------- stage 2b: fold FF into V table ------------------------------
__global__ void build_vf(const float* __restrict__ Wf,
                         const float* __restrict__ bf) {
    int tv = blockIdx.x;            // 0..519
    int j  = threadIdx.x;           // 0..31
    const float* vr = g_VT + tv * NEMB;
    float acc = bf[j];
#pragma unroll
    for (int c = 0; c < NEMB; c++)
        acc = fmaf(vr[c], Wf[c * NEMB + j], acc);
    g_VF[tv * NEMB + j] = acc;
}

// ---------------- stage 3: main ----------------------------------------------
// smem float offsets
#define VFP  34
#define SY   0                           // Y: 512 rows x 33 float2 (hi,lo)
#define SVF  (512 * 66)                  // 33792 ; VF 520 x 34
#define SBH  (SVF + NTV * VFP)           // 51472 ; Wl-hi tf32 [32][72]
#define SBLO (SBH + 32 * 72)             // 53776 ; Wl-lo tf32 [32][72]
#define SW64 (SBLO + 32 * 72)            // 56080 ; Wl[:,64]
#define SW0  (SW64 + 32)                 // 56112 ; Wl[:,0]
#define SBIAS (SW0 + 32)                 // 56144 ; bl (68 padded)
#define SMEM_FLOATS (SBIAS + 68)         // 56212
#define SMEM_BYTES  (SMEM_FLOATS * 4)    // 224,848 bytes

template<int TA>
__device__ __forceinline__ void scalar_pair(const float4* __restrict__ QK4,
                                            float* __restrict__ sm,
                                            const int* __restrict__ tok,
                                            int tid, float* __restrict__ out,
                                            int gb, int nb)
{
    constexpr int TB = TA + 1;
    const int baseA = TA * (TA + 1) / 2;
    const int baseB = baseA + TA + 1;
    const int rA = tok[TA] * VOCAB;
    const int rB = tok[TB] * VOCAB;

    float4 sA = make_float4(0.f, 0.f, 0.f, 0.f);
    float4 sB = make_float4(0.f, 0.f, 0.f, 0.f);
    u64 hA[16], hB[16];
#pragma unroll
    for (int g = 0; g < 16; g++) { hA[g] = 0ULL; hB[g] = 0ULL; }

    // ---- shared-s combine: VF row loaded ONCE for both rows TA,TB ----
#pragma unroll
    for (int s = 0; s <= TA; s++) {
        float4 eA = __ldg(&QK4[(baseA + s) * (VOCAB * VOCAB) + rA + tok[s]]);
        float4 eB = __ldg(&QK4[(baseB + s) * (VOCAB * VOCAB) + rB + tok[s]]);
        sA.x += eA.x; sA.y += eA.y; sA.z += eA.z; sA.w += eA.w;
        sB.x += eB.x; sB.y += eB.y; sB.z += eB.z; sB.w += eB.w;
        u64 wA[4] = { pk2(eA.x, eA.x), pk2(eA.y, eA.y),
                      pk2(eA.z, eA.z), pk2(eA.w, eA.w) };
        u64 wB[4] = { pk2(eB.x, eB.x), pk2(eB.y, eB.y),
                      pk2(eB.z, eB.z), pk2(eB.w, eB.w) };
        const u64* v2 = (const u64*)(sm + SVF + (s * VOCAB + tok[s]) * VFP);
#pragma unroll
        for (int g = 0; g < 16; g++) {
            u64 r = v2[g];
            hA[g] = fma2(wA[g >> 2], r, hA[g]);
            hB[g] = fma2(wB[g >> 2], r, hB[g]);
        }
    }
    {   // extra s = TB term, row B only
        float4 eB = __ldg(&QK4[(baseB + TB) * (VOCAB * VOCAB) + rB + tok[TB]]);
        sB.x += eB.x; sB.y += eB.y; sB.z += eB.z; sB.w += eB.w;
        u64 wB[4] = { pk2(eB.x, eB.x), pk2(eB.y, eB.y),
                      pk2(eB.z, eB.z), pk2(eB.w, eB.w) };
        const u64* v2 = (const u64*)(sm + SVF + (TB * VOCAB + tok[TB]) * VFP);
#pragma unroll
        for (int g = 0; g < 16; g++)
            hB[g] = fma2(wB[g >> 2], v2[g], hB[g]);
    }

    // ---- post-hoc softmax normalization + relu ----
    u64 iA[4], iB[4];
    {
        float a = __fdividef(1.f, sA.x), b = __fdividef(1.f, sA.y);
        float c = __fdividef(1.f, sA.z), d = __fdividef(1.f, sA.w);
        iA[0] = pk2(a, a); iA[1] = pk2(b, b); iA[2] = pk2(c, c); iA[3] = pk2(d, d);
        a = __fdividef(1.f, sB.x); b = __fdividef(1.f, sB.y);
        c = __fdividef(1.f, sB.z); d = __fdividef(1.f, sB.w);
        iB[0] = pk2(a, a); iB[1] = pk2(b, b); iB[2] = pk2(c, c); iB[3] = pk2(d, d);
    }
    float yA[32], yB[32];
#pragma unroll
    for (int g = 0; g < 16; g++) {
        float u, v;
        upk2(u, v, mul2(hA[g], iA[g >> 2]));
        yA[2 * g] = fmaxf(u, 0.f); yA[2 * g + 1] = fmaxf(v, 0.f);
        upk2(u, v, mul2(hB[g], iB[g >> 2]));
        yB[2 * g] = fmaxf(u, 0.f); yB[2 * g + 1] = fmaxf(v, 0.f);
    }

    // ---- scalar columns: rowA col 64, rowB col 0 (alignment scheme) ----
    float zA = sm[SBIAS + 64];
    float zB = sm[SBIAS + 0];
#pragma unroll
    for (int j = 0; j < 32; j++) {
        zA = fmaf(yA[j], sm[SW64 + j], zA);
        zB = fmaf(yB[j], sm[SW0 + j], zB);
    }
    if (gb < nb) {
        __stcs(out + (size_t)gb * 520 + TA * 65 + 64, zA);
        __stcs(out + (size_t)gb * 520 + TB * 65, zB);
    }

    // ---- tf32 split + store Y rows (tid -> row TA ; tid+256 -> row TB) ----
    float* rowA = sm + SY + tid * 66;
    float* rowB = sm + SY + (tid + 256) * 66;
#pragma unroll
    for (int j = 0; j < 32; j++) {
        unsigned int h = tf32h(yA[j]);
        unsigned int l = tf32h(yA[j] - __uint_as_float(h));
        *(uint2*)(rowA + 2 * j) = make_uint2(h, l);
        h = tf32h(yB[j]);
        l = tf32h(yB[j] - __uint_as_float(h));
        *(uint2*)(rowB + 2 * j) = make_uint2(h, l);
    }
}

__device__ __forceinline__ void mma_phase(float* __restrict__ sm,
                                          float* __restrict__ out,
                                          int tid, int TA, int gbase, int nb)
{
    int wid = tid >> 5, lane = tid & 31;
    int g = lane >> 2, t = lane & 3;
#pragma unroll
    for (int mt = 0; mt < 4; mt++) {
        int r0 = wid * 64 + mt * 16;
        int rowbit = r0 >> 8;            // 0 -> row TA (even), 1 -> TA+1 (odd)
        int trow = TA + rowbit;
        int bbase = r0 & 255;
        int csh = rowbit;                // odd rows: mma covers cols 1..64

        // ---- A fragments (hi+lo in one LDS.64 each) ----
        unsigned int ah[4][4], al[4][4];
        const float* yb = sm + SY + (r0 + g) * 66;
#pragma unroll
        for (int k = 0; k < 4; k++) {
            uint2 p0 = *(const uint2*)(yb + 2 * (k * 8 + t));
            uint2 p1 = *(const uint2*)(yb + 8 * 66 + 2 * (k * 8 + t));
            uint2 p2 = *(const uint2*)(yb + 2 * (k * 8 + t + 4));
            uint2 p3 = *(const uint2*)(yb + 8 * 66 + 2 * (k * 8 + t + 4));
            ah[k][0] = p0.x; al[k][0] = p0.y;
            ah[k][1] = p1.x; al[k][1] = p1.y;
            ah[k][2] = p2.x; al[k][2] = p2.y;
            ah[k][3] = p3.x; al[k][3] = p3.y;
        }

        int gb0 = gbase + bbase + g;
#pragma unroll 2
        for (int nt = 0; nt < 8; nt++) {
            int n0 = nt * 8 + csh;
            unsigned int bh[4][2], blo[4][2];
#pragma unroll
            for (int k = 0; k < 4; k++) {
                int rk0 = (k * 8 + t) * 72 + n0 + g;
                int rk1 = (k * 8 + t + 4) * 72 + n0 + g;
                bh[k][0]  = __float_as_uint(sm[SBH + rk0]);
                bh[k][1]  = __float_as_uint(sm[SBH + rk1]);
                blo[k][0] = __float_as_uint(sm[SBLO + rk0]);
                blo[k][1] = __float_as_uint(sm[SBLO + rk1]);
            }
            float d[4][4];
#pragma unroll
            for (int k = 0; k < 4; k++) {
                d[k][0] = 0.f; d[k][1] = 0.f; d[k][2] = 0.f; d[k][3] = 0.f;
            }
#pragma unroll
            for (int k = 0; k < 4; k++) mma8(d[k], ah[k], bh[k]);   // Ah*Bh
#pragma unroll
            for (int k = 0; k < 4; k++) mma8(d[k], al[k], bh[k]);   // Al*Bh
#pragma unroll
            for (int k = 0; k < 4; k++) mma8(d[k], ah[k], blo[k]);  // Ah*Bl

            int c0 = n0 + t * 2;
            float bi0 = sm[SBIAS + c0], bi1 = sm[SBIAS + c0 + 1];
            float z0 = d[0][0] + d[1][0] + d[2][0] + d[3][0] + bi0;
            float z1 = d[0][1] + d[1][1] + d[2][1] + d[3][1] + bi1;
            float z2 = d[0][2] + d[1][2] + d[2][2] + d[3][2] + bi0;
            float z3 = d[0][3] + d[1][3] + d[2][3] + d[3][3] + bi1;

            size_t a0 = (size_t)gb0 * 520 + (size_t)trow * 65 + c0;
            if (gb0 < nb)
                __stcs((float2*)(out + a0), make_float2(z0, z1));
            if (gb0 + 8 < nb)
                __stcs((float2*)(out + a0 + 8 * 520), make_float2(z2, z3));
        }
    }
}

__global__ __launch_bounds__(256, 1)
void bigram_main(const int* __restrict__ idx,
                 const float* __restrict__ Wl, const float* __restrict__ bl,
                 float* __restrict__ out, int nb) {
    extern __shared__ float sm[];
    int tid = threadIdx.x;

    // --- cooperative smem fill ---
    for (int r = tid; r < NTV; r += 256) {
        const u64* src = (const u64*)(g_VF + r * NEMB);
        u64* dst = (u64*)(sm + SVF + r * VFP);
#pragma unroll
        for (int g = 0; g < 16; g++) dst[g] = src[g];
    }
    // Wl tf32 hi/lo split: [32][72] pad, cols 0..64 valid
    for (int i = tid; i < 32 * VOCAB; i += 256) {
        int k = i / VOCAB, n = i - k * VOCAB;
        float w = Wl[i];
        unsigned int h = tf32h(w);
        unsigned int l = tf32h(w - __uint_as_float(h));
        sm[SBH + k * 72 + n]  = __uint_as_float(h);
        sm[SBLO + k * 72 + n] = __uint_as_float(l);
    }
    if (tid < 32) {
        sm[SW64 + tid] = Wl[tid * VOCAB + 64];
        sm[SW0 + tid]  = Wl[tid * VOCAB];
    }
    if (tid < 68) sm[SBIAS + tid] = (tid < 65) ? bl[tid] : 0.f;
    __syncthreads();

    const float4* QK4 = (const float4*)g_QK;
    int ntile = (nb + 255) >> 8;

    for (int tile = blockIdx.x; tile < ntile; tile += gridDim.x) {
        int gbase = tile << 8;
        int b = gbase + tid;
        int bc = min(b, nb - 1);
        int tok[8];
        {
            const int4* pa = (const int4*)(idx + (size_t)bc * 8);
            int4 x0 = __ldg(pa), x1 = __ldg(pa + 1);
            tok[0] = x0.x; tok[1] = x0.y; tok[2] = x0.z; tok[3] = x0.w;
            tok[4] = x1.x; tok[5] = x1.y; tok[6] = x1.z; tok[7] = x1.w;
        }

#define WAVE(TA)                                                            \
        scalar_pair<TA>(QK4, sm, tok, tid, out, b, nb);                     \
        __syncthreads();                                                    \
        mma_phase(sm, out, tid, TA, gbase, nb);                             \
        __syncthreads();

        WAVE(0) WAVE(2) WAVE(4) WAVE(6)
#undef WAVE
    }
}

// ---------------------------------------------------------------------------
extern "C" void kernel_launch(void* const* d_in, const int* in_sizes, int n_in,
                              void* d_out, int out_size) {
    const int*   idx     = (const int*)  d_in[0];
    const float* tok_emb = (const float*)d_in[1];
    const float* pos_emb = (const float*)d_in[2];
    const float* Wq      = (const float*)d_in[3];
    const float* Wk      = (const float*)d_in[4];
    const float* Wv      = (const float*)d_in[5];
    const float* Wf      = (const float*)d_in[6];
    const float* bf      = (const float*)d_in[7];
    const float* Wl      = (const float*)d_in[8];
    const float* bl      = (const float*)d_in[9];
    float* out = (float*)d_out;

    int nb = in_sizes[0] / TBLK;   // 131072

    cudaFuncSetAttribute(bigram_main,
                         cudaFuncAttributeMaxDynamicSharedMemorySize, SMEM_BYTES);

    int dev = 0, nsm = 148;
    cudaGetDevice(&dev);
    cudaDeviceGetAttribute(&nsm, cudaDevAttrMultiProcessorCount, dev);

    build_qkv<<<NTV, 32>>>(tok_emb, pos_emb, Wq, Wk, Wv);
    build_qk<<<dim3(VOCAB, NPAIR), 256>>>();
    build_vf<<<NTV, 32>>>(Wf, bf);

    bigram_main<<<nsm, 256, SMEM_BYTES>>>(idx, Wl, bl, out, nb);
}